// round 15
// baseline (speedup 1.0000x reference)
#include <cuda_runtime.h>
#include <cstdint>
#include <cstdio>

#define NN 100000
#define NE 600000
#define HH 128
#define KPX 176

// ---------------- static device buffers (allocation-free scratch) ----------
__device__ __align__(16) float g_h   [(size_t)NN*HH];
__device__ __align__(16) float g_agg0[(size_t)NN*HH];
__device__ __align__(16) float g_agg1[(size_t)NN*HH];
__device__ __align__(16) float g_hr  [(size_t)NN*HH];
__device__ __align__(16) float g_hh2 [(size_t)NN*HH];
__device__ __align__(16) float g_hp  [(size_t)NN*HH];
__device__ __align__(16) float g_att [(size_t)NN*HH];
__device__ __align__(16) float g_gi  [(size_t)NN*3*HH];
__device__ __align__(16) float g_gh  [(size_t)NN*3*HH];
__device__ __align__(16) float g_f   [(size_t)NN*64];
__device__ __align__(16) float g_wf  [HH*HH];
__device__ float         g_s0[NN];
__device__ float         g_s1[NN];
__device__ unsigned      g_ntbits[NN];
__device__ int           g_degtot[NN];
__device__ int           g_degrec[NN];
__device__ unsigned char g_upd[NN];
__device__ unsigned      g_hist0[2048];
__device__ unsigned      g_histB[2*2048];
__device__ unsigned      g_histC[2*1024];
__device__ unsigned      g_prefix[2];
__device__ unsigned      g_krem[2];
__device__ float         g_med;
__device__ unsigned      g_ntmin_u, g_ntmax_u;
__device__ float         g_bvo[HH];
__device__ float         g_b0sum[HH];

// ---- bf16 hi/lo split operand buffers --------------------------------------
__device__ __align__(16) uint16_t g_xh [(size_t)NN*KPX], g_xl [(size_t)NN*KPX];
__device__ __align__(16) uint16_t g_hh [(size_t)NN*HH],  g_hl [(size_t)NN*HH];
__device__ __align__(16) uint16_t g_mh [(size_t)NN*HH],  g_ml [(size_t)NN*HH];
__device__ __align__(16) uint16_t g_a0h[(size_t)NN*HH],  g_a0l[(size_t)NN*HH];
__device__ __align__(16) uint16_t g_a1h[(size_t)NN*HH],  g_a1l[(size_t)NN*HH];
__device__ __align__(16) uint16_t g_hph[(size_t)NN*HH],  g_hpl[(size_t)NN*HH];
__device__ __align__(16) uint16_t g_hqh[(size_t)NN*HH],  g_hql[(size_t)NN*HH];
__device__ __align__(16) uint16_t g_Winh[128*KPX], g_Winl[128*KPX];
__device__ __align__(16) uint16_t g_Wihh[384*HH],  g_Wihl[384*HH];
__device__ __align__(16) uint16_t g_Whhh[384*HH],  g_Whhl[384*HH];
__device__ __align__(16) uint16_t g_Wgrh[128*HH],  g_Wgrl[128*HH];
__device__ __align__(16) uint16_t g_Wghh[128*HH],  g_Wghl[128*HH];
__device__ __align__(16) uint16_t g_wfh [128*HH],  g_wfl [128*HH];
__device__ __align__(16) uint16_t g_W1h [64*HH],   g_W1l [64*HH];

__device__ __forceinline__ float wredsum(float v){
    #pragma unroll
    for (int o=16;o;o>>=1) v += __shfl_xor_sync(0xffffffffu, v, o);
    return v;
}
__device__ __forceinline__ uint32_t smem_u32(const void* p){
    uint32_t a;
    asm("{ .reg .u64 t; cvta.to.shared.u64 t, %1; cvt.u32.u64 %0, t; }" : "=r"(a) : "l"(p));
    return a;
}
__device__ __forceinline__ uint32_t bf2(float e0, float e1){
    uint32_t r;
    asm("cvt.rn.bf16x2.f32 %0, %2, %1;" : "=r"(r) : "f"(e0), "f"(e1));
    return r;
}
__device__ __forceinline__ uint32_t hipack(float a, float b){
    uint32_t r;
    asm("prmt.b32 %0,%1,%2,0x7632;" : "=r"(r) : "r"(__float_as_uint(a)), "r"(__float_as_uint(b)));
    return r;
}
__device__ __forceinline__ float lopart(float v){
    return v - __uint_as_float(__float_as_uint(v) & 0xffff0000u);
}

#define LDSM4(d0,d1,d2,d3,addr) \
    asm volatile("ldmatrix.sync.aligned.m8n8.x4.shared.b16 {%0,%1,%2,%3}, [%4];" \
        : "=r"(d0),"=r"(d1),"=r"(d2),"=r"(d3) : "r"(addr))

#define MMA(c,a0,a1,a2,a3,b0,b1) \
    asm volatile("mma.sync.aligned.m16n8k16.row.col.f32.bf16.bf16.f32 " \
        "{%0,%1,%2,%3},{%4,%5,%6,%7},{%8,%9},{%0,%1,%2,%3};" \
        : "+f"((c)[0]),"+f"((c)[1]),"+f"((c)[2]),"+f"((c)[3]) \
        : "r"(a0),"r"(a1),"r"(a2),"r"(a3),"r"(b0),"r"(b1))

#define CPA16(dst,src,sz) \
    asm volatile("cp.async.cg.shared.global [%0],[%1],16,%2;" :: "r"(dst),"l"(src),"r"(sz))

// ---------------- init ------------------------------------------------------
__global__ void k_init(){
    size_t idx = (size_t)blockIdx.x*blockDim.x + threadIdx.x;
    size_t str = (size_t)gridDim.x*blockDim.x;
    for (size_t i=idx; i<(size_t)NN*HH; i+=str){ g_agg0[i]=0.f; g_agg1[i]=0.f; }
    for (size_t i=idx; i<NN; i+=str){ g_ntbits[i]=0u; g_degtot[i]=0; g_degrec[i]=0; g_upd[i]=0; }
    for (size_t i=idx; i<2048; i+=str) g_hist0[i]=0u;
    if (idx==0){ g_ntmin_u=0xFFFFFFFFu; g_ntmax_u=0u; }
}

// ---------------- b0sum = b_in + b_time --------------------------------------
__global__ void k_bsum(const float* __restrict__ a, const float* __restrict__ b){
    int j = threadIdx.x;
    g_b0sum[j] = a[j] + b[j];
}

// ---------------- split: fp32 [R,C] -> bf16 hi/lo [R,Cp] ---------------------
__global__ void k_split(const float* __restrict__ src, int R, int C, int Cp,
                        uint16_t* __restrict__ oh, uint16_t* __restrict__ ol){
    int idx = blockIdx.x*blockDim.x + threadIdx.x;
    int half = Cp>>1;
    if (idx >= R*half) return;
    int r = idx/half, p = idx - r*half;
    int c0 = p*2;
    float v0 = (c0   < C) ? src[(size_t)r*C + c0]   : 0.f;
    float v1 = (c0+1 < C) ? src[(size_t)r*C + c0+1] : 0.f;
    ((uint32_t*)oh)[idx] = hipack(v0, v1);
    ((uint32_t*)ol)[idx] = bf2(lopart(v0), lopart(v1));
}

// ---------------- split2: (agg + s*h) -> bf16 hi/lo --------------------------
__global__ void k_split2(const float* __restrict__ agg, const float* __restrict__ s,
                         const float* __restrict__ h,
                         uint16_t* __restrict__ oh, uint16_t* __restrict__ ol){
    int idx = blockIdx.x*blockDim.x + threadIdx.x;
    if (idx >= NN*64) return;
    int r = idx>>6;
    float sv = s[r];
    size_t e = (size_t)idx*2;
    float v0 = agg[e]   + sv*h[e];
    float v1 = agg[e+1] + sv*h[e+1];
    ((uint32_t*)oh)[idx] = hipack(v0, v1);
    ((uint32_t*)ol)[idx] = bf2(lopart(v0), lopart(v1));
}

// ---------------- HMMA bf16 3-split GEMM (pre-split operands, cp.async) -----
template<int MODE>
__global__ __launch_bounds__(256,2) void k_mma2(
        const uint16_t* __restrict__ Ah, const uint16_t* __restrict__ Al,
        const uint16_t* __restrict__ Bh, const uint16_t* __restrict__ Bl,
        float* __restrict__ C, int M, int N, int Kp,
        const float* __restrict__ e1wt, const float* __restrict__ e1memp,
        uint16_t* __restrict__ OutH, uint16_t* __restrict__ OutL)
{
    __shared__ __align__(16) uint16_t sm[2][4][128*24];
    const int tid = threadIdx.x, lane = tid&31, wid = tid>>5;
    const int bm = blockIdx.y*128, bn = blockIdx.x*128;
    const int nch = Kp>>4;

    float acc[2][8][4];
    #pragma unroll
    for (int i=0;i<2;i++)
        #pragma unroll
        for (int j=0;j<8;j++)
            #pragma unroll
            for (int q=0;q<4;q++) acc[i][j][q]=0.f;

    const int srow = tid>>1, seg = tid&1;
    const int gmq = bm + srow, gnq = bn + srow;
    const int szA = (gmq < M) ? 16 : 0;
    const int szB = (gnq < N) ? 16 : 0;
    const size_t offAs = (size_t)(gmq < M ? gmq : 0)*Kp + seg*8;
    const size_t offBs = (size_t)(gnq < N ? gnq : 0)*Kp + seg*8;
    const int sdst = srow*24 + seg*8;

#define ISSUE(c, st) do{                                                     \
        size_t ko = (size_t)(c)*16;                                          \
        CPA16(smem_u32(&sm[st][0][sdst]), Ah + offAs + ko, szA);             \
        CPA16(smem_u32(&sm[st][1][sdst]), Al + offAs + ko, szA);             \
        CPA16(smem_u32(&sm[st][2][sdst]), Bh + offBs + ko, szB);             \
        CPA16(smem_u32(&sm[st][3][sdst]), Bl + offBs + ko, szB);             \
        asm volatile("cp.async.commit_group;" ::: "memory");                 \
    } while(0)

    const int wm = (wid>>1)*32, wn = (wid&1)*64;
    const int r8 = lane&7, grp = lane>>3;
    const uint32_t offA0 = (uint32_t)(((wm +      r8 + ((grp&1)<<3))*24 + ((grp>>1)<<3))*2);
    const uint32_t offA1 = offA0 + 16u*24u*2u;
    const uint32_t offB  = (uint32_t)(((wn + r8 + (((grp>>1)&1)<<3))*24 + ((grp&1)<<3))*2);

    ISSUE(0, 0);
    for (int c=0;c<nch;c++){
        if (c+1<nch){
            ISSUE(c+1, (c+1)&1);
            asm volatile("cp.async.wait_group 1;" ::: "memory");
        } else {
            asm volatile("cp.async.wait_group 0;" ::: "memory");
        }
        __syncthreads();
        const int st = c&1;
        const uint32_t bAh = smem_u32(&sm[st][0][0]);
        const uint32_t bAl = smem_u32(&sm[st][1][0]);
        const uint32_t bBh = smem_u32(&sm[st][2][0]);
        const uint32_t bBl = smem_u32(&sm[st][3][0]);
        uint32_t aH[2][4], aL[2][4];
        LDSM4(aH[0][0],aH[0][1],aH[0][2],aH[0][3], bAh + offA0);
        LDSM4(aH[1][0],aH[1][1],aH[1][2],aH[1][3], bAh + offA1);
        LDSM4(aL[0][0],aL[0][1],aL[0][2],aL[0][3], bAl + offA0);
        LDSM4(aL[1][0],aL[1][1],aL[1][2],aL[1][3], bAl + offA1);
        #pragma unroll
        for (int jt=0;jt<4;jt++){
            uint32_t bH[4], bL[4];
            uint32_t ob = offB + (uint32_t)(jt*16*24*2);
            LDSM4(bH[0],bH[1],bH[2],bH[3], bBh + ob);
            LDSM4(bL[0],bL[1],bL[2],bL[3], bBl + ob);
            #pragma unroll
            for (int i=0;i<2;i++){
                #pragma unroll
                for (int jj=0;jj<2;jj++){
                    float* cc = acc[i][jt*2+jj];
                    MMA(cc, aH[i][0],aH[i][1],aH[i][2],aH[i][3], bH[jj*2],bH[jj*2+1]);
                    MMA(cc, aL[i][0],aL[i][1],aL[i][2],aL[i][3], bH[jj*2],bH[jj*2+1]);
                    MMA(cc, aH[i][0],aH[i][1],aH[i][2],aH[i][3], bL[jj*2],bL[jj*2+1]);
                }
            }
        }
        __syncthreads();
    }
#undef ISSUE

    const int cr = lane>>2, ccol = (lane&3)*2;
    float tmin=0.f, tmax=0.f;
    if (MODE==1){ tmin = __uint_as_float(g_ntmin_u); tmax = __uint_as_float(g_ntmax_u); }
    #pragma unroll
    for (int i=0;i<2;i++){
        #pragma unroll
        for (int j=0;j<8;j++){
            int gmm = bm + wm + i*16 + cr;
            int gnn = bn + wn + j*8 + ccol;
            float* cc = acc[i][j];
            if (gnn >= N) continue;
            if (MODE==0){
                if (gmm < M)   *(float2*)&C[(size_t)gmm*N+gnn]     = make_float2(cc[0],cc[1]);
                if (gmm+8 < M) *(float2*)&C[(size_t)(gmm+8)*N+gnn] = make_float2(cc[2],cc[3]);
            } else {
                float b0 = g_b0sum[gnn], b1 = g_b0sum[gnn+1];
                float w0 = e1wt[gnn],    w1 = e1wt[gnn+1];
                #pragma unroll
                for (int hh=0;hh<2;hh++){
                    int gr = gmm + hh*8;
                    if (gr >= M) continue;
                    float nt = __uint_as_float(g_ntbits[gr]);
                    float ntn = (tmax>tmin) ? (nt-tmin)/(tmax-tmin+1e-8f) : nt;
                    float v0 = fmaxf(cc[hh*2]   + b0 + ntn*w0, 0.f) + e1memp[(size_t)gr*HH+gnn];
                    float v1 = fmaxf(cc[hh*2+1] + b1 + ntn*w1, 0.f) + e1memp[(size_t)gr*HH+gnn+1];
                    *(float2*)&C[(size_t)gr*N+gnn] = make_float2(v0,v1);
                    size_t pi = ((size_t)gr*HH + gnn)>>1;
                    ((uint32_t*)OutH)[pi] = hipack(v0,v1);
                    ((uint32_t*)OutL)[pi] = bf2(lopart(v0), lopart(v1));
                }
            }
        }
    }
}

// ---------------- edge pass ---------------------------------------------------
__global__ void k_edge1a(const int* __restrict__ row, const int* __restrict__ col,
                         const float* __restrict__ ts){
    int e = blockIdx.x*blockDim.x + threadIdx.x;
    if (e>=NE) return;
    unsigned key = __float_as_uint(ts[e]);
    int r = row[e], c = col[e];
    g_upd[r]=1; g_upd[c]=1;
    atomicMax(&g_ntbits[c], key);
    atomicAdd(&g_degtot[c], 1);
}

__global__ void k_hist0(const float* __restrict__ ts){
    __shared__ unsigned sh[2048];
    for (int i=threadIdx.x;i<2048;i+=blockDim.x) sh[i]=0u;
    __syncthreads();
    int idx = blockIdx.x*blockDim.x + threadIdx.x;
    int str = gridDim.x*blockDim.x;
    for (int e=idx; e<NE; e+=str){
        unsigned key = __float_as_uint(ts[e]);
        atomicAdd(&sh[key>>21], 1u);
    }
    __syncthreads();
    for (int i=threadIdx.x;i<2048;i+=blockDim.x)
        if (sh[i]) atomicAdd(&g_hist0[i], sh[i]);
}

__global__ void k_scan0(){
    __shared__ unsigned sh[2048];
    __shared__ unsigned cum[2049];
    int t = threadIdx.x;
    for (int i=t;i<2048;i+=blockDim.x) sh[i]=g_hist0[i];
    __syncthreads();
    if (t==0){ unsigned run=0; for (int i=0;i<2048;i++){ cum[i]=run; run+=sh[i]; } cum[2048]=run; }
    __syncthreads();
    for (int i=t;i<2048;i+=blockDim.x){
        #pragma unroll
        for (int s=0;s<2;s++){
            unsigned k = 299999u + (unsigned)s;
            if (k>=cum[i] && k<cum[i+1]){ g_prefix[s]=(unsigned)i; g_krem[s]=k-cum[i]; }
        }
    }
    for (int i=t;i<4096;i+=blockDim.x) g_histB[i]=0u;
}

__global__ void k_hist1(const float* __restrict__ ts){
    int e = blockIdx.x*blockDim.x + threadIdx.x;
    if (e>=NE) return;
    unsigned p0 = g_prefix[0], p1 = g_prefix[1];
    unsigned key = __float_as_uint(ts[e]);
    unsigned hi = key>>21;
    unsigned bin = (key>>10)&0x7FFu;
    if (hi==p0) atomicAdd(&g_histB[bin], 1u);
    if (hi==p1) atomicAdd(&g_histB[2048+bin], 1u);
}

__global__ void k_scan1(){
    __shared__ unsigned sh[2048];
    __shared__ unsigned cum[2049];
    __shared__ unsigned skrem, spfx;
    int t = threadIdx.x;
    for (int s=0;s<2;s++){
        for (int i=t;i<2048;i+=blockDim.x) sh[i]=g_histB[s*2048+i];
        __syncthreads();
        if (t==0){
            unsigned run=0; for (int i=0;i<2048;i++){ cum[i]=run; run+=sh[i]; } cum[2048]=run;
            skrem = g_krem[s]; spfx = g_prefix[s];
        }
        __syncthreads();
        unsigned k = skrem, pf = spfx;
        for (int i=t;i<2048;i+=blockDim.x)
            if (k>=cum[i] && k<cum[i+1]){ g_prefix[s]=(pf<<11)|(unsigned)i; g_krem[s]=k-cum[i]; }
        __syncthreads();
    }
    for (int i=t;i<2048;i+=blockDim.x) g_histC[i]=0u;
}

__global__ void k_hist2(const float* __restrict__ ts){
    int e = blockIdx.x*blockDim.x + threadIdx.x;
    if (e>=NE) return;
    unsigned p0 = g_prefix[0], p1 = g_prefix[1];
    unsigned key = __float_as_uint(ts[e]);
    unsigned hi = key>>10;
    unsigned bin = key&1023u;
    if (hi==p0) atomicAdd(&g_histC[bin], 1u);
    if (hi==p1) atomicAdd(&g_histC[1024+bin], 1u);
}

__global__ void k_scan2(){
    __shared__ unsigned sh[1024];
    __shared__ unsigned cum[1025];
    __shared__ unsigned skrem, spfx;
    __shared__ float vals[2];
    int t = threadIdx.x;
    for (int s=0;s<2;s++){
        for (int i=t;i<1024;i+=blockDim.x) sh[i]=g_histC[s*1024+i];
        __syncthreads();
        if (t==0){
            unsigned run=0; for (int i=0;i<1024;i++){ cum[i]=run; run+=sh[i]; } cum[1024]=run;
            skrem = g_krem[s]; spfx = g_prefix[s];
        }
        __syncthreads();
        unsigned k = skrem, pf = spfx;
        for (int i=t;i<1024;i+=blockDim.x)
            if (k>=cum[i] && k<cum[i+1]) vals[s] = __uint_as_float((pf<<10)|(unsigned)i);
        __syncthreads();
    }
    if (t==0) g_med = 0.5f*(vals[0]+vals[1]);
}

__global__ void k_ntmm(){
    int i = blockIdx.x*blockDim.x + threadIdx.x;
    unsigned mn = 0xFFFFFFFFu, mx = 0u;
    if (i<NN){ unsigned v = g_ntbits[i]; mn=v; mx=v; }
    #pragma unroll
    for (int o=16;o;o>>=1){
        unsigned a = __shfl_xor_sync(0xffffffffu, mn, o); mn = (a<mn)?a:mn;
        unsigned b = __shfl_xor_sync(0xffffffffu, mx, o); mx = (b>mx)?b:mx;
    }
    if ((threadIdx.x&31)==0){
        atomicMin(&g_ntmin_u, mn);
        atomicMax(&g_ntmax_u, mx);
    }
}

__global__ void k_e2(const float* __restrict__ b_ih, const float* __restrict__ b_hh,
                     const float* __restrict__ mem, float* __restrict__ out_nm){
    size_t idx = (size_t)blockIdx.x*blockDim.x + threadIdx.x;
    if (idx >= (size_t)NN*HH) return;
    int i = (int)(idx>>7), j = (int)(idx&127);
    size_t base = (size_t)i*384;
    float ir = g_gi[base+j]     + b_ih[j];
    float iz = g_gi[base+128+j] + b_ih[128+j];
    float ic = g_gi[base+256+j] + b_ih[256+j];
    float hr = g_gh[base+j]     + b_hh[j];
    float hz = g_gh[base+128+j] + b_hh[128+j];
    float hc = g_gh[base+256+j] + b_hh[256+j];
    float r = 1.f/(1.f+expf(-(ir+hr)));
    float z = 1.f/(1.f+expf(-(iz+hz)));
    float c = tanhf(ic + r*hc);
    float m = mem[idx];
    out_nm[idx] = g_upd[i] ? ((1.f-z)*c + z*m) : m;
}

__global__ void k_deg(const int* __restrict__ col, const float* __restrict__ ts){
    int e = blockIdx.x*blockDim.x + threadIdx.x;
    if (e>=NE) return;
    if (ts[e] >= g_med) atomicAdd(&g_degrec[col[e]], 1);
}

__global__ void k_sscale(){
    int i = blockIdx.x*blockDim.x + threadIdx.x;
    if (i>=NN) return;
    int drec = g_degrec[i], dtot = g_degtot[i];
    g_s0[i] = 1.f/(float)(drec+1);
    g_s1[i] = 1.f/(float)(dtot-drec+1);
}

__global__ void k_scatter(const int* __restrict__ row, const int* __restrict__ col,
                          const float* __restrict__ ts){
    int gw = (blockIdx.x*blockDim.x + threadIdx.x)>>5;
    if (gw>=NE) return;
    int lane = threadIdx.x&31;
    int r = row[gw], c = col[gw];
    float t = ts[gw];
    float med = g_med;
    int rec = (t >= med);
    int drr = g_degrec[r], drc = g_degrec[c];
    float dr = (float)((rec ? drr : g_degtot[r]-drr) + 1);
    float dc = (float)((rec ? drc : g_degtot[c]-drc) + 1);
    float coef = rsqrtf(dr)*rsqrtf(dc);
    float4 hv = *(const float4*)&g_h[(size_t)r*HH + lane*4];
    float* dst = (rec ? g_agg0 : g_agg1) + (size_t)c*HH + lane*4;
    asm volatile("red.global.add.v4.f32 [%0], {%1,%2,%3,%4};"
                 :: "l"(dst), "f"(hv.x*coef), "f"(hv.y*coef), "f"(hv.z*coef), "f"(hv.w*coef)
                 : "memory");
}

// ---------------- E4: softmax combine + LN (+ hp bf16 split) -----------------
__global__ void k_e4(const float* __restrict__ b_gr, const float* __restrict__ b_gh,
                     const float* __restrict__ lg, const float* __restrict__ lb){
    int w = (blockIdx.x*blockDim.x + threadIdx.x)>>5;
    if (w>=NN) return;
    int lane = threadIdx.x&31;
    size_t base = (size_t)w*HH;
    int j0 = lane*4;
    float4 r4 = *(const float4*)&g_hr[base+j0];
    float4 h4 = *(const float4*)&g_hh2[base+j0];
    float4 bg = *(const float4*)&b_gr[j0];
    float4 bh = *(const float4*)&b_gh[j0];
    float hr[4] = {r4.x+bg.x, r4.y+bg.y, r4.z+bg.z, r4.w+bg.w};
    float hh[4] = {h4.x+bh.x, h4.y+bh.y, h4.z+bh.z, h4.w+bh.w};
    float s0 = wredsum(hr[0]+hr[1]+hr[2]+hr[3]);
    float s1 = wredsum(hh[0]+hh[1]+hh[2]+hh[3]);
    float m0 = s0*(1.f/128.f), m1 = s1*(1.f/128.f);
    float mx = fmaxf(m0,m1);
    float e0 = expf(m0-mx), e1 = expf(m1-mx);
    float inv = 1.f/(e0+e1);
    float w0 = e0*inv, w1 = e1*inv;
    float c[4]; float s=0.f;
    #pragma unroll
    for (int q=0;q<4;q++){ c[q] = w0*hr[q] + w1*hh[q]; s += c[q]; }
    s = wredsum(s);
    float mu = s*(1.f/128.f);
    float vs=0.f;
    #pragma unroll
    for (int q=0;q<4;q++){ float d=c[q]-mu; vs += d*d; }
    vs = wredsum(vs);
    float istd = rsqrtf(vs*(1.f/128.f) + 1e-5f);
    float4 g4 = *(const float4*)&lg[j0];
    float4 l4 = *(const float4*)&lb[j0];
    float o0 = (c[0]-mu)*istd*g4.x + l4.x;
    float o1 = (c[1]-mu)*istd*g4.y + l4.y;
    float o2 = (c[2]-mu)*istd*g4.z + l4.z;
    float o3 = (c[3]-mu)*istd*g4.w + l4.w;
    *(float4*)&g_hp[base+j0] = make_float4(o0,o1,o2,o3);
    size_t pi = (base+j0)>>1;
    ((uint32_t*)g_hph)[pi]   = hipack(o0,o1);
    ((uint32_t*)g_hph)[pi+1] = hipack(o2,o3);
    ((uint32_t*)g_hpl)[pi]   = bf2(lopart(o0), lopart(o1));
    ((uint32_t*)g_hpl)[pi+1] = bf2(lopart(o2), lopart(o3));
}

__global__ void k_bvo(const float* __restrict__ bv, const float* __restrict__ Wo,
                      const float* __restrict__ bo){
    int j = threadIdx.x;
    float a = bo[j];
    for (int k=0;k<HH;k++) a += bv[k]*Wo[j*HH+k];
    g_bvo[j] = a;
}

__global__ void k_wf(const float* __restrict__ Wo, const float* __restrict__ Wv){
    __shared__ float srow[HH];
    int i = blockIdx.x;
    int k = threadIdx.x;
    srow[k] = Wo[i*HH + k];
    __syncthreads();
    float a = 0.f;
    #pragma unroll 8
    for (int j=0;j<HH;j++) a += srow[j]*Wv[j*HH + k];
    g_wf[i*HH + k] = a;
}

// ---------------- E6: LN(hp + att + bvo) -> hq bf16 split --------------------
__global__ void k_e6(const float* __restrict__ lg, const float* __restrict__ lb){
    int w = (blockIdx.x*blockDim.x + threadIdx.x)>>5;
    if (w>=NN) return;
    int lane = threadIdx.x&31;
    size_t base = (size_t)w*HH;
    int j0 = lane*4;
    float4 p4 = *(const float4*)&g_hp[base+j0];
    float4 a4 = *(const float4*)&g_att[base+j0];
    float4 b4 = *(const float4*)&g_bvo[j0];
    float c[4] = {p4.x+a4.x+b4.x, p4.y+a4.y+b4.y, p4.z+a4.z+b4.z, p4.w+a4.w+b4.w};
    float s = wredsum(c[0]+c[1]+c[2]+c[3]);
    float mu = s*(1.f/128.f);
    float vs=0.f;
    #pragma unroll
    for (int q=0;q<4;q++){ float d=c[q]-mu; vs += d*d; }
    vs = wredsum(vs);
    float istd = rsqrtf(vs*(1.f/128.f) + 1e-5f);
    float4 g4 = *(const float4*)&lg[j0];
    float4 l4 = *(const float4*)&lb[j0];
    float o0 = (c[0]-mu)*istd*g4.x + l4.x;
    float o1 = (c[1]-mu)*istd*g4.y + l4.y;
    float o2 = (c[2]-mu)*istd*g4.z + l4.z;
    float o3 = (c[3]-mu)*istd*g4.w + l4.w;
    size_t pi = (base+j0)>>1;
    ((uint32_t*)g_hqh)[pi]   = hipack(o0,o1);
    ((uint32_t*)g_hqh)[pi+1] = hipack(o2,o3);
    ((uint32_t*)g_hql)[pi]   = bf2(lopart(o0), lopart(o1));
    ((uint32_t*)g_hql)[pi+1] = bf2(lopart(o2), lopart(o3));
}

__global__ void k_final(const float* __restrict__ b1, const float* __restrict__ W2,
                        const float* __restrict__ b2, float* __restrict__ out){
    int w = (blockIdx.x*blockDim.x + threadIdx.x)>>5;
    if (w>=NN) return;
    int lane = threadIdx.x&31;
    float f0 = fmaxf(g_f[(size_t)w*64 + lane]      + b1[lane],    0.f);
    float f1 = fmaxf(g_f[(size_t)w*64 + 32 + lane] + b1[32+lane], 0.f);
    float l0 = f0*W2[lane]    + f1*W2[32+lane];
    float l1 = f0*W2[64+lane] + f1*W2[96+lane];
    l0 = wredsum(l0); l1 = wredsum(l1);
    if (lane==0){
        out[(size_t)w*2]   = l0 + b2[0];
        out[(size_t)w*2+1] = l1 + b2[1];
    }
}

// ---------------- host driver ------------------------------------------------
static float* symf(const void* s){ void* p=nullptr; cudaGetSymbolAddress(&p, s); return (float*)p; }
static uint16_t* symu(const void* s){ void* p=nullptr; cudaGetSymbolAddress(&p, s); return (uint16_t*)p; }

extern "C" void kernel_launch(void* const* d_in, const int* in_sizes, int n_in,
                              void* d_out, int out_size){
    const float* x      = (const float*)d_in[0];
    const int*   ei     = (const int*)  d_in[1];
    const float* ts     = (const float*)d_in[2];
    const float* mem    = (const float*)d_in[3];
    const float* W_in   = (const float*)d_in[4];
    const float* b_in   = (const float*)d_in[5];
    const float* W_time = (const float*)d_in[6];
    const float* b_time = (const float*)d_in[7];
    const float* W_ih   = (const float*)d_in[8];
    const float* W_hh   = (const float*)d_in[9];
    const float* b_ih   = (const float*)d_in[10];
    const float* b_hh   = (const float*)d_in[11];
    const float* W_gr   = (const float*)d_in[12];
    const float* b_gr   = (const float*)d_in[13];
    const float* W_gh   = (const float*)d_in[14];
    const float* b_gh   = (const float*)d_in[15];
    const float* ln_pa_g= (const float*)d_in[16];
    const float* ln_pa_b= (const float*)d_in[17];
    const float* Wv     = (const float*)d_in[18];
    const float* bv     = (const float*)d_in[19];
    const float* Wo     = (const float*)d_in[20];
    const float* bo     = (const float*)d_in[21];
    const float* ln_at_g= (const float*)d_in[22];
    const float* ln_at_b= (const float*)d_in[23];
    const float* W1     = (const float*)d_in[24];
    const float* b1     = (const float*)d_in[25];
    const float* W2     = (const float*)d_in[26];
    const float* b2     = (const float*)d_in[27];
    const int* row = ei;
    const int* col = ei + NE;

    float* out        = (float*)d_out;
    float* out_logits = out;
    float* out_newmem = out + 2*(size_t)NN;

    float* p_h    = symf(g_h);
    float* p_agg0 = symf(g_agg0);
    float* p_agg1 = symf(g_agg1);
    float* p_hr   = symf(g_hr);
    float* p_hh2  = symf(g_hh2);
    float* p_att  = symf(g_att);
    float* p_gi   = symf(g_gi);
    float* p_gh   = symf(g_gh);
    float* p_f    = symf(g_f);
    float* p_wf   = symf(g_wf);
    float* p_s0   = symf(g_s0);
    float* p_s1   = symf(g_s1);

    uint16_t *p_xh=symu(g_xh), *p_xl=symu(g_xl);
    uint16_t *p_hh=symu(g_hh), *p_hl=symu(g_hl);
    uint16_t *p_mh=symu(g_mh), *p_ml=symu(g_ml);
    uint16_t *p_a0h=symu(g_a0h), *p_a0l=symu(g_a0l);
    uint16_t *p_a1h=symu(g_a1h), *p_a1l=symu(g_a1l);
    uint16_t *p_hph=symu(g_hph), *p_hpl=symu(g_hpl);
    uint16_t *p_hqh=symu(g_hqh), *p_hql=symu(g_hql);
    uint16_t *p_Winh=symu(g_Winh), *p_Winl=symu(g_Winl);
    uint16_t *p_Wihh=symu(g_Wihh), *p_Wihl=symu(g_Wihl);
    uint16_t *p_Whhh=symu(g_Whhh), *p_Whhl=symu(g_Whhl);
    uint16_t *p_Wgrh=symu(g_Wgrh), *p_Wgrl=symu(g_Wgrl);
    uint16_t *p_Wghh=symu(g_Wghh), *p_Wghl=symu(g_Wghl);
    uint16_t *p_wfh=symu(g_wfh),   *p_wfl=symu(g_wfl);
    uint16_t *p_W1h=symu(g_W1h),   *p_W1l=symu(g_W1l);

    const int EB  = (NE+255)/256;
    const int EWB = (NE*32+255)/256;
    const int NHB = (int)(((size_t)NN*HH+255)/256);
    const int NWB = (NN*32+255)/256;
    const int MY  = (NN+127)/128;

    k_init<<<1024,256>>>();
    k_wf<<<HH,HH>>>(Wo, Wv);
    k_bvo<<<1,128>>>(bv, Wo, bo);
    k_bsum<<<1,128>>>(b_in, b_time);

    k_split<<<(128*(KPX/2)+255)/256,256>>>(W_in, 128, 166, KPX, p_Winh, p_Winl);
    k_split<<<(384*64+255)/256,256>>>(W_ih, 384, 128, 128, p_Wihh, p_Wihl);
    k_split<<<(384*64+255)/256,256>>>(W_hh, 384, 128, 128, p_Whhh, p_Whhl);
    k_split<<<(128*64+255)/256,256>>>(W_gr, 128, 128, 128, p_Wgrh, p_Wgrl);
    k_split<<<(128*64+255)/256,256>>>(W_gh, 128, 128, 128, p_Wghh, p_Wghl);
    k_split<<<(128*64+255)/256,256>>>(p_wf, 128, 128, 128, p_wfh, p_wfl);
    k_split<<<( 64*64+255)/256,256>>>(W1,    64, 128, 128, p_W1h, p_W1l);
    k_split<<<(NN*(KPX/2)+255)/256,256>>>(x,   NN, 166, KPX, p_xh, p_xl);
    k_split<<<(NN*64+255)/256,256>>>(mem, NN, 128, 128, p_mh, p_ml);

    k_edge1a<<<EB,256>>>(row,col,ts);
    k_hist0<<<264,256>>>(ts);
    k_scan0<<<1,256>>>();
    k_hist1<<<EB,256>>>(ts);
    k_scan1<<<1,256>>>();
    k_hist2<<<EB,256>>>(ts);
    k_scan2<<<1,256>>>();
    k_ntmm<<<(NN+255)/256,256>>>();

    // h = relu(x@W_in^T + b_in + ntn*wt + bt) + memory (e1 fused, emits h hi/lo)
    k_mma2<1><<<dim3(1,MY),256>>>(p_xh, p_xl, p_Winh, p_Winl, p_h, NN, 128, KPX,
                                  W_time, mem, p_hh, p_hl);

    // GRU
    k_mma2<0><<<dim3(3,MY),256>>>(p_hh, p_hl, p_Wihh, p_Wihl, p_gi, NN, 384, 128,
                                  nullptr, nullptr, nullptr, nullptr);
    k_mma2<0><<<dim3(3,MY),256>>>(p_mh, p_ml, p_Whhh, p_Whhl, p_gh, NN, 384, 128,
                                  nullptr, nullptr, nullptr, nullptr);
    k_e2<<<NHB,256>>>(b_ih, b_hh, mem, out_newmem);

    // GCN paths
    k_deg<<<EB,256>>>(col, ts);
    k_sscale<<<(NN+255)/256,256>>>();
    k_scatter<<<EWB,256>>>(row, col, ts);
    k_split2<<<(NN*64+255)/256,256>>>(p_agg0, p_s0, p_h, p_a0h, p_a0l);
    k_split2<<<(NN*64+255)/256,256>>>(p_agg1, p_s1, p_h, p_a1h, p_a1l);
    k_mma2<0><<<dim3(1,MY),256>>>(p_a0h, p_a0l, p_Wgrh, p_Wgrl, p_hr,  NN, 128, 128,
                                  nullptr, nullptr, nullptr, nullptr);
    k_mma2<0><<<dim3(1,MY),256>>>(p_a1h, p_a1l, p_Wghh, p_Wghl, p_hh2, NN, 128, 128,
                                  nullptr, nullptr, nullptr, nullptr);
    k_e4<<<NWB,256>>>(b_gr, b_gh, ln_pa_g, ln_pa_b);

    // attention (query path cancels; Wv/Wo fused): att = hp @ (Wo Wv)^T
    k_mma2<0><<<dim3(1,MY),256>>>(p_hph, p_hpl, p_wfh, p_wfl, p_att, NN, 128, 128,
                                  nullptr, nullptr, nullptr, nullptr);
    k_e6<<<NWB,256>>>(ln_at_g, ln_at_b);

    // classifier
    k_mma2<0><<<dim3(1,MY),256>>>(p_hqh, p_hql, p_W1h, p_W1l, p_f, NN, 64, 128,
                                  nullptr, nullptr, nullptr, nullptr);
    k_final<<<NWB,256>>>(b1, W2, b2, out_logits);

    (void)in_sizes; (void)n_in; (void)out_size;
}

// round 17
// speedup vs baseline: 1.1232x; 1.1232x over previous
#include <cuda_runtime.h>
#include <cstdint>
#include <cstdio>

#define NN 100000
#define NE 600000
#define HH 128

// ---------------- static device buffers (allocation-free scratch) ----------
__device__ __align__(16) float g_h   [(size_t)NN*HH];
__device__ __align__(16) float g_agg0[(size_t)NN*HH];
__device__ __align__(16) float g_agg1[(size_t)NN*HH];
__device__ __align__(16) float g_hr  [(size_t)NN*HH];
__device__ __align__(16) float g_hh2 [(size_t)NN*HH];
__device__ __align__(16) float g_hp  [(size_t)NN*HH];
__device__ __align__(16) float g_att [(size_t)NN*HH];
__device__ __align__(16) float g_hq  [(size_t)NN*HH];
__device__ __align__(16) float g_gi  [(size_t)NN*3*HH];
__device__ __align__(16) float g_gh  [(size_t)NN*3*HH];
__device__ __align__(16) float g_f   [(size_t)NN*64];
__device__ __align__(16) float g_wf  [HH*HH];
__device__ float         g_s0[NN];
__device__ float         g_s1[NN];
__device__ unsigned      g_ntbits[NN];
__device__ int           g_degtot[NN];
__device__ int           g_degrec[NN];
__device__ unsigned char g_upd[NN];
__device__ unsigned      g_hist0[2048];
__device__ unsigned      g_histB[2*2048];
__device__ unsigned      g_histC[2*1024];
__device__ unsigned      g_prefix[2];
__device__ unsigned      g_krem[2];
__device__ float         g_med;
__device__ unsigned      g_ntmin_u, g_ntmax_u;
__device__ float         g_bvo[HH];
__device__ float         g_b0sum[HH];

__device__ __forceinline__ float wredsum(float v){
    #pragma unroll
    for (int o=16;o;o>>=1) v += __shfl_xor_sync(0xffffffffu, v, o);
    return v;
}
__device__ __forceinline__ uint32_t smem_u32(const void* p){
    uint32_t a;
    asm("{ .reg .u64 t; cvta.to.shared.u64 t, %1; cvt.u32.u64 %0, t; }" : "=r"(a) : "l"(p));
    return a;
}
__device__ __forceinline__ uint32_t bf2(float e0, float e1){
    uint32_t r;
    asm("cvt.rn.bf16x2.f32 %0, %2, %1;" : "=r"(r) : "f"(e0), "f"(e1));
    return r;
}
__device__ __forceinline__ uint32_t hipack(float a, float b){
    uint32_t r;
    asm("prmt.b32 %0,%1,%2,0x7632;" : "=r"(r) : "r"(__float_as_uint(a)), "r"(__float_as_uint(b)));
    return r;
}
__device__ __forceinline__ float lopart(float v){
    return v - __uint_as_float(__float_as_uint(v) & 0xffff0000u);
}

#define LDSM4(d0,d1,d2,d3,addr) \
    asm volatile("ldmatrix.sync.aligned.m8n8.x4.shared.b16 {%0,%1,%2,%3}, [%4];" \
        : "=r"(d0),"=r"(d1),"=r"(d2),"=r"(d3) : "r"(addr))

#define MMA(c,a0,a1,a2,a3,b0,b1) \
    asm volatile("mma.sync.aligned.m16n8k16.row.col.f32.bf16.bf16.f32 " \
        "{%0,%1,%2,%3},{%4,%5,%6,%7},{%8,%9},{%0,%1,%2,%3};" \
        : "+f"((c)[0]),"+f"((c)[1]),"+f"((c)[2]),"+f"((c)[3]) \
        : "r"(a0),"r"(a1),"r"(a2),"r"(a3),"r"(b0),"r"(b1))

// ---------------- init ------------------------------------------------------
__global__ void k_init(){
    size_t idx = (size_t)blockIdx.x*blockDim.x + threadIdx.x;
    size_t str = (size_t)gridDim.x*blockDim.x;
    for (size_t i=idx; i<(size_t)NN*HH; i+=str){ g_agg0[i]=0.f; g_agg1[i]=0.f; }
    for (size_t i=idx; i<NN; i+=str){ g_ntbits[i]=0u; g_degtot[i]=0; g_degrec[i]=0; g_upd[i]=0; }
    for (size_t i=idx; i<2048; i+=str) g_hist0[i]=0u;
    if (idx==0){ g_ntmin_u=0xFFFFFFFFu; g_ntmax_u=0u; }
}

// ---------------- b0sum = b_in + b_time --------------------------------------
__global__ void k_bsum(const float* __restrict__ a, const float* __restrict__ b){
    int j = threadIdx.x;
    g_b0sum[j] = a[j] + b[j];
}

// ---------------- HMMA bf16 3-split GEMM, in-kernel convert, double-buffered
// C[M,N] = (A + rs.*A2)[M,K] * B[N,K]^T.  128x128 block, 256 thr, warp 32x64.
// Per 16-k chunk: fp32 -> hi/lo bf16 into stage smem (stride 24 bf16);
// ONE __syncthreads per chunk (write next stage while others compute current).
// MODE 1: fused e1 epilogue: C = relu(acc + b0sum + ntn*wt) + mem.
template<int MODE>
__global__ __launch_bounds__(256,2) void k_mma(const float* __restrict__ A,
        const float* __restrict__ A2, const float* __restrict__ rs,
        const float* __restrict__ B, float* __restrict__ C,
        int M, int N, int K,
        const float* __restrict__ e1wt, const float* __restrict__ e1mem)
{
    extern __shared__ __align__(16) uint16_t smbuf[];   // 2 stages x 4 arrays x 128*24
    const int tid = threadIdx.x, lane = tid&31, wid = tid>>5;
    const int bm = blockIdx.y*128, bn = blockIdx.x*128;
    const int row = tid>>1, half = tid&1;
    const int gm = bm + row;
    const int gn = bn + row;
    const bool kv4 = ((K & 3) == 0);

    float acc[2][8][4];
    #pragma unroll
    for (int i=0;i<2;i++)
        #pragma unroll
        for (int j=0;j<8;j++)
            #pragma unroll
            for (int q=0;q<4;q++) acc[i][j][q]=0.f;

    const int nch = (K+15)>>4;
    float a_st[8], b_st[8];

#define LOADC(c) do{                                                          \
        int gk0 = (c)*16 + half*8;                                            \
        if (gm < M){                                                          \
            if (kv4 && gk0+8 <= K){                                           \
                float4 v0 = *(const float4*)&A[(size_t)gm*K+gk0];             \
                float4 v1 = *(const float4*)&A[(size_t)gm*K+gk0+4];           \
                if (A2){                                                      \
                    float s = rs[gm];                                         \
                    float4 w0 = *(const float4*)&A2[(size_t)gm*K+gk0];        \
                    float4 w1 = *(const float4*)&A2[(size_t)gm*K+gk0+4];      \
                    v0.x+=s*w0.x; v0.y+=s*w0.y; v0.z+=s*w0.z; v0.w+=s*w0.w;   \
                    v1.x+=s*w1.x; v1.y+=s*w1.y; v1.z+=s*w1.z; v1.w+=s*w1.w;   \
                }                                                             \
                a_st[0]=v0.x; a_st[1]=v0.y; a_st[2]=v0.z; a_st[3]=v0.w;       \
                a_st[4]=v1.x; a_st[5]=v1.y; a_st[6]=v1.z; a_st[7]=v1.w;       \
            } else {                                                          \
                float s = A2 ? rs[gm] : 0.f;                                  \
                _Pragma("unroll")                                             \
                for (int e=0;e<8;e++){                                        \
                    int gk = gk0+e;                                           \
                    float v = 0.f;                                            \
                    if (gk < K){                                              \
                        v = A[(size_t)gm*K+gk];                               \
                        if (A2) v += s*A2[(size_t)gm*K+gk];                   \
                    }                                                         \
                    a_st[e] = v;                                              \
                }                                                             \
            }                                                                 \
        } else {                                                              \
            _Pragma("unroll") for (int e=0;e<8;e++) a_st[e]=0.f;              \
        }                                                                     \
        if (gn < N){                                                          \
            if (kv4 && gk0+8 <= K){                                           \
                float4 v0 = *(const float4*)&B[(size_t)gn*K+gk0];             \
                float4 v1 = *(const float4*)&B[(size_t)gn*K+gk0+4];           \
                b_st[0]=v0.x; b_st[1]=v0.y; b_st[2]=v0.z; b_st[3]=v0.w;       \
                b_st[4]=v1.x; b_st[5]=v1.y; b_st[6]=v1.z; b_st[7]=v1.w;       \
            } else {                                                          \
                _Pragma("unroll")                                             \
                for (int e=0;e<8;e++){                                        \
                    int gk = gk0+e;                                           \
                    b_st[e] = (gk < K) ? B[(size_t)gn*K+gk] : 0.f;            \
                }                                                             \
            }                                                                 \
        } else {                                                              \
            _Pragma("unroll") for (int e=0;e<8;e++) b_st[e]=0.f;              \
        }                                                                     \
    } while(0)

#define STOREC(st) do{                                                        \
        uint16_t* sp = smbuf + (st)*12288;                                    \
        uint32_t ha[4], la[4], hb[4], lb[4];                                  \
        _Pragma("unroll")                                                     \
        for (int q=0;q<4;q++){                                                \
            ha[q] = hipack(a_st[2*q], a_st[2*q+1]);                           \
            la[q] = bf2(lopart(a_st[2*q]), lopart(a_st[2*q+1]));              \
            hb[q] = hipack(b_st[2*q], b_st[2*q+1]);                           \
            lb[q] = bf2(lopart(b_st[2*q]), lopart(b_st[2*q+1]));              \
        }                                                                     \
        int so = row*24 + half*8;                                             \
        *(uint4*)&sp[so]        = make_uint4(ha[0],ha[1],ha[2],ha[3]);        \
        *(uint4*)&sp[3072+so]   = make_uint4(la[0],la[1],la[2],la[3]);        \
        *(uint4*)&sp[6144+so]   = make_uint4(hb[0],hb[1],hb[2],hb[3]);        \
        *(uint4*)&sp[9216+so]   = make_uint4(lb[0],lb[1],lb[2],lb[3]);        \
    } while(0)

    const int wm = (wid>>1)*32, wn = (wid&1)*64;
    const int r8 = lane&7, grp = lane>>3;
    const uint32_t sbase = smem_u32(smbuf);
    // A frag: mats (mlo,klo),(mhi,klo),(mlo,khi),(mhi,khi)
    const uint32_t offA0 = (uint32_t)(((wm +      r8 + ((grp&1)<<3))*24 + ((grp>>1)<<3))*2);
    const uint32_t offA1 = offA0 + 16u*24u*2u;
    // B frag: mats (nlo,klo),(nlo,khi),(nhi,klo),(nhi,khi)
    const uint32_t offB  = (uint32_t)(((wn + r8 + (((grp>>1)&1)<<3))*24 + ((grp&1)<<3))*2);

    LOADC(0);
    STOREC(0);
    __syncthreads();
    for (int c=0;c<nch;c++){
        if (c+1<nch){ LOADC(c+1); }
        const uint32_t st = (uint32_t)(c&1)*24576u;
        const uint32_t bAh = sbase + st;
        const uint32_t bAl = bAh + 6144u;
        const uint32_t bBh = bAh + 12288u;
        const uint32_t bBl = bAh + 18432u;
        uint32_t aH[2][4], aL[2][4];
        LDSM4(aH[0][0],aH[0][1],aH[0][2],aH[0][3], bAh + offA0);
        LDSM4(aH[1][0],aH[1][1],aH[1][2],aH[1][3], bAh + offA1);
        LDSM4(aL[0][0],aL[0][1],aL[0][2],aL[0][3], bAl + offA0);
        LDSM4(aL[1][0],aL[1][1],aL[1][2],aL[1][3], bAl + offA1);
        #pragma unroll
        for (int jt=0;jt<4;jt++){
            uint32_t bH[4], bL[4];
            uint32_t ob = offB + (uint32_t)(jt*16*24*2);
            LDSM4(bH[0],bH[1],bH[2],bH[3], bBh + ob);
            LDSM4(bL[0],bL[1],bL[2],bL[3], bBl + ob);
            #pragma unroll
            for (int i=0;i<2;i++){
                #pragma unroll
                for (int jj=0;jj<2;jj++){
                    float* cc = acc[i][jt*2+jj];
                    MMA(cc, aH[i][0],aH[i][1],aH[i][2],aH[i][3], bH[jj*2],bH[jj*2+1]);
                    MMA(cc, aL[i][0],aL[i][1],aL[i][2],aL[i][3], bH[jj*2],bH[jj*2+1]);
                    MMA(cc, aH[i][0],aH[i][1],aH[i][2],aH[i][3], bL[jj*2],bL[jj*2+1]);
                }
            }
        }
        if (c+1<nch){ STOREC((c+1)&1); }
        __syncthreads();
    }
#undef LOADC
#undef STOREC

    // epilogue
    const int cr = lane>>2, ccol = (lane&3)*2;
    float tmin=0.f, tmax=0.f;
    if (MODE==1){ tmin = __uint_as_float(g_ntmin_u); tmax = __uint_as_float(g_ntmax_u); }
    #pragma unroll
    for (int i=0;i<2;i++){
        #pragma unroll
        for (int j=0;j<8;j++){
            int gmm = bm + wm + i*16 + cr;
            int gnn = bn + wn + j*8 + ccol;
            float* cc = acc[i][j];
            if (gnn >= N) continue;
            if (MODE==0){
                if (gmm < M)   *(float2*)&C[(size_t)gmm*N+gnn]     = make_float2(cc[0],cc[1]);
                if (gmm+8 < M) *(float2*)&C[(size_t)(gmm+8)*N+gnn] = make_float2(cc[2],cc[3]);
            } else {
                float b0 = g_b0sum[gnn], b1 = g_b0sum[gnn+1];
                float w0 = e1wt[gnn],    w1 = e1wt[gnn+1];
                #pragma unroll
                for (int hh=0;hh<2;hh++){
                    int gr = gmm + hh*8;
                    if (gr >= M) continue;
                    float nt = __uint_as_float(g_ntbits[gr]);
                    float ntn = (tmax>tmin) ? (nt-tmin)/(tmax-tmin+1e-8f) : nt;
                    float v0 = fmaxf(cc[hh*2]   + b0 + ntn*w0, 0.f) + e1mem[(size_t)gr*HH+gnn];
                    float v1 = fmaxf(cc[hh*2+1] + b1 + ntn*w1, 0.f) + e1mem[(size_t)gr*HH+gnn+1];
                    *(float2*)&C[(size_t)gr*N+gnn] = make_float2(v0,v1);
                }
            }
        }
    }
}

// ---------------- edge pass ---------------------------------------------------
__global__ void k_edge1a(const int* __restrict__ row, const int* __restrict__ col,
                         const float* __restrict__ ts){
    int e = blockIdx.x*blockDim.x + threadIdx.x;
    if (e>=NE) return;
    unsigned key = __float_as_uint(ts[e]);   // ts >= 0 -> uint order == float order
    int r = row[e], c = col[e];
    g_upd[r]=1; g_upd[c]=1;
    atomicMax(&g_ntbits[c], key);
    atomicAdd(&g_degtot[c], 1);
}

__global__ void k_hist0(const float* __restrict__ ts){
    __shared__ unsigned sh[2048];
    for (int i=threadIdx.x;i<2048;i+=blockDim.x) sh[i]=0u;
    __syncthreads();
    int idx = blockIdx.x*blockDim.x + threadIdx.x;
    int str = gridDim.x*blockDim.x;
    for (int e=idx; e<NE; e+=str){
        unsigned key = __float_as_uint(ts[e]);
        atomicAdd(&sh[key>>21], 1u);
    }
    __syncthreads();
    for (int i=threadIdx.x;i<2048;i+=blockDim.x)
        if (sh[i]) atomicAdd(&g_hist0[i], sh[i]);
}

__global__ void k_scan0(){
    __shared__ unsigned sh[2048];
    __shared__ unsigned cum[2049];
    int t = threadIdx.x;
    for (int i=t;i<2048;i+=blockDim.x) sh[i]=g_hist0[i];
    __syncthreads();
    if (t==0){ unsigned run=0; for (int i=0;i<2048;i++){ cum[i]=run; run+=sh[i]; } cum[2048]=run; }
    __syncthreads();
    for (int i=t;i<2048;i+=blockDim.x){
        #pragma unroll
        for (int s=0;s<2;s++){
            unsigned k = 299999u + (unsigned)s;
            if (k>=cum[i] && k<cum[i+1]){ g_prefix[s]=(unsigned)i; g_krem[s]=k-cum[i]; }
        }
    }
    for (int i=t;i<4096;i+=blockDim.x) g_histB[i]=0u;
}

__global__ void k_hist1(const float* __restrict__ ts){
    int e = blockIdx.x*blockDim.x + threadIdx.x;
    if (e>=NE) return;
    unsigned p0 = g_prefix[0], p1 = g_prefix[1];
    unsigned key = __float_as_uint(ts[e]);
    unsigned hi = key>>21;
    unsigned bin = (key>>10)&0x7FFu;
    if (hi==p0) atomicAdd(&g_histB[bin], 1u);
    if (hi==p1) atomicAdd(&g_histB[2048+bin], 1u);
}

__global__ void k_scan1(){
    __shared__ unsigned sh[2048];
    __shared__ unsigned cum[2049];
    __shared__ unsigned skrem, spfx;
    int t = threadIdx.x;
    for (int s=0;s<2;s++){
        for (int i=t;i<2048;i+=blockDim.x) sh[i]=g_histB[s*2048+i];
        __syncthreads();
        if (t==0){
            unsigned run=0; for (int i=0;i<2048;i++){ cum[i]=run; run+=sh[i]; } cum[2048]=run;
            skrem = g_krem[s]; spfx = g_prefix[s];
        }
        __syncthreads();
        unsigned k = skrem, pf = spfx;
        for (int i=t;i<2048;i+=blockDim.x)
            if (k>=cum[i] && k<cum[i+1]){ g_prefix[s]=(pf<<11)|(unsigned)i; g_krem[s]=k-cum[i]; }
        __syncthreads();
    }
    for (int i=t;i<2048;i+=blockDim.x) g_histC[i]=0u;
}

__global__ void k_hist2(const float* __restrict__ ts){
    int e = blockIdx.x*blockDim.x + threadIdx.x;
    if (e>=NE) return;
    unsigned p0 = g_prefix[0], p1 = g_prefix[1];
    unsigned key = __float_as_uint(ts[e]);
    unsigned hi = key>>10;
    unsigned bin = key&1023u;
    if (hi==p0) atomicAdd(&g_histC[bin], 1u);
    if (hi==p1) atomicAdd(&g_histC[1024+bin], 1u);
}

__global__ void k_scan2(){
    __shared__ unsigned sh[1024];
    __shared__ unsigned cum[1025];
    __shared__ unsigned skrem, spfx;
    __shared__ float vals[2];
    int t = threadIdx.x;
    for (int s=0;s<2;s++){
        for (int i=t;i<1024;i+=blockDim.x) sh[i]=g_histC[s*1024+i];
        __syncthreads();
        if (t==0){
            unsigned run=0; for (int i=0;i<1024;i++){ cum[i]=run; run+=sh[i]; } cum[1024]=run;
            skrem = g_krem[s]; spfx = g_prefix[s];
        }
        __syncthreads();
        unsigned k = skrem, pf = spfx;
        for (int i=t;i<1024;i+=blockDim.x)
            if (k>=cum[i] && k<cum[i+1]) vals[s] = __uint_as_float((pf<<10)|(unsigned)i);
        __syncthreads();
    }
    if (t==0) g_med = 0.5f*(vals[0]+vals[1]);
}

__global__ void k_ntmm(){
    int i = blockIdx.x*blockDim.x + threadIdx.x;
    unsigned mn = 0xFFFFFFFFu, mx = 0u;
    if (i<NN){ unsigned v = g_ntbits[i]; mn=v; mx=v; }
    #pragma unroll
    for (int o=16;o;o>>=1){
        unsigned a = __shfl_xor_sync(0xffffffffu, mn, o); mn = (a<mn)?a:mn;
        unsigned b = __shfl_xor_sync(0xffffffffu, mx, o); mx = (b>mx)?b:mx;
    }
    if ((threadIdx.x&31)==0){
        atomicMin(&g_ntmin_u, mn);
        atomicMax(&g_ntmax_u, mx);
    }
}

__global__ void k_e2(const float* __restrict__ b_ih, const float* __restrict__ b_hh,
                     const float* __restrict__ mem, float* __restrict__ out_nm){
    size_t idx = (size_t)blockIdx.x*blockDim.x + threadIdx.x;
    if (idx >= (size_t)NN*HH) return;
    int i = (int)(idx>>7), j = (int)(idx&127);
    size_t base = (size_t)i*384;
    float ir = g_gi[base+j]     + b_ih[j];
    float iz = g_gi[base+128+j] + b_ih[128+j];
    float ic = g_gi[base+256+j] + b_ih[256+j];
    float hr = g_gh[base+j]     + b_hh[j];
    float hz = g_gh[base+128+j] + b_hh[128+j];
    float hc = g_gh[base+256+j] + b_hh[256+j];
    float r = 1.f/(1.f+expf(-(ir+hr)));
    float z = 1.f/(1.f+expf(-(iz+hz)));
    float c = tanhf(ic + r*hc);
    float m = mem[idx];
    out_nm[idx] = g_upd[i] ? ((1.f-z)*c + z*m) : m;
}

__global__ void k_deg(const int* __restrict__ col, const float* __restrict__ ts){
    int e = blockIdx.x*blockDim.x + threadIdx.x;
    if (e>=NE) return;
    if (ts[e] >= g_med) atomicAdd(&g_degrec[col[e]], 1);
}

__global__ void k_sscale(){
    int i = blockIdx.x*blockDim.x + threadIdx.x;
    if (i>=NN) return;
    int drec = g_degrec[i], dtot = g_degtot[i];
    g_s0[i] = 1.f/(float)(drec+1);
    g_s1[i] = 1.f/(float)(dtot-drec+1);
}

__global__ void k_scatter(const int* __restrict__ row, const int* __restrict__ col,
                          const float* __restrict__ ts){
    int gw = (blockIdx.x*blockDim.x + threadIdx.x)>>5;
    if (gw>=NE) return;
    int lane = threadIdx.x&31;
    int r = row[gw], c = col[gw];
    float t = ts[gw];
    float med = g_med;
    int rec = (t >= med);
    int drr = g_degrec[r], drc = g_degrec[c];
    float dr = (float)((rec ? drr : g_degtot[r]-drr) + 1);
    float dc = (float)((rec ? drc : g_degtot[c]-drc) + 1);
    float coef = rsqrtf(dr)*rsqrtf(dc);
    float4 hv = *(const float4*)&g_h[(size_t)r*HH + lane*4];
    float* dst = (rec ? g_agg0 : g_agg1) + (size_t)c*HH + lane*4;
    asm volatile("red.global.add.v4.f32 [%0], {%1,%2,%3,%4};"
                 :: "l"(dst), "f"(hv.x*coef), "f"(hv.y*coef), "f"(hv.z*coef), "f"(hv.w*coef)
                 : "memory");
}

__global__ void k_e4(const float* __restrict__ b_gr, const float* __restrict__ b_gh,
                     const float* __restrict__ lg, const float* __restrict__ lb){
    int w = (blockIdx.x*blockDim.x + threadIdx.x)>>5;
    if (w>=NN) return;
    int lane = threadIdx.x&31;
    size_t base = (size_t)w*HH;
    int j0 = lane*4;
    float4 r4 = *(const float4*)&g_hr[base+j0];
    float4 h4 = *(const float4*)&g_hh2[base+j0];
    float4 bg = *(const float4*)&b_gr[j0];
    float4 bh = *(const float4*)&b_gh[j0];
    float hr[4] = {r4.x+bg.x, r4.y+bg.y, r4.z+bg.z, r4.w+bg.w};
    float hh[4] = {h4.x+bh.x, h4.y+bh.y, h4.z+bh.z, h4.w+bh.w};
    float s0 = wredsum(hr[0]+hr[1]+hr[2]+hr[3]);
    float s1 = wredsum(hh[0]+hh[1]+hh[2]+hh[3]);
    float m0 = s0*(1.f/128.f), m1 = s1*(1.f/128.f);
    float mx = fmaxf(m0,m1);
    float e0 = expf(m0-mx), e1 = expf(m1-mx);
    float inv = 1.f/(e0+e1);
    float w0 = e0*inv, w1 = e1*inv;
    float c[4]; float s=0.f;
    #pragma unroll
    for (int q=0;q<4;q++){ c[q] = w0*hr[q] + w1*hh[q]; s += c[q]; }
    s = wredsum(s);
    float mu = s*(1.f/128.f);
    float vs=0.f;
    #pragma unroll
    for (int q=0;q<4;q++){ float d=c[q]-mu; vs += d*d; }
    vs = wredsum(vs);
    float istd = rsqrtf(vs*(1.f/128.f) + 1e-5f);
    float4 g4 = *(const float4*)&lg[j0];
    float4 l4 = *(const float4*)&lb[j0];
    float o0 = (c[0]-mu)*istd*g4.x + l4.x;
    float o1 = (c[1]-mu)*istd*g4.y + l4.y;
    float o2 = (c[2]-mu)*istd*g4.z + l4.z;
    float o3 = (c[3]-mu)*istd*g4.w + l4.w;
    *(float4*)&g_hp[base+j0] = make_float4(o0,o1,o2,o3);
}

__global__ void k_bvo(const float* __restrict__ bv, const float* __restrict__ Wo,
                      const float* __restrict__ bo){
    int j = threadIdx.x;
    float a = bo[j];
    for (int k=0;k<HH;k++) a += bv[k]*Wo[j*HH+k];
    g_bvo[j] = a;
}

__global__ void k_wf(const float* __restrict__ Wo, const float* __restrict__ Wv){
    __shared__ float srow[HH];
    int i = blockIdx.x;
    int k = threadIdx.x;
    srow[k] = Wo[i*HH + k];
    __syncthreads();
    float a = 0.f;
    #pragma unroll 8
    for (int j=0;j<HH;j++) a += srow[j]*Wv[j*HH + k];
    g_wf[i*HH + k] = a;
}

__global__ void k_e6(const float* __restrict__ lg, const float* __restrict__ lb){
    int w = (blockIdx.x*blockDim.x + threadIdx.x)>>5;
    if (w>=NN) return;
    int lane = threadIdx.x&31;
    size_t base = (size_t)w*HH;
    int j0 = lane*4;
    float4 p4 = *(const float4*)&g_hp[base+j0];
    float4 a4 = *(const float4*)&g_att[base+j0];
    float4 b4 = *(const float4*)&g_bvo[j0];
    float c[4] = {p4.x+a4.x+b4.x, p4.y+a4.y+b4.y, p4.z+a4.z+b4.z, p4.w+a4.w+b4.w};
    float s = wredsum(c[0]+c[1]+c[2]+c[3]);
    float mu = s*(1.f/128.f);
    float vs=0.f;
    #pragma unroll
    for (int q=0;q<4;q++){ float d=c[q]-mu; vs += d*d; }
    vs = wredsum(vs);
    float istd = rsqrtf(vs*(1.f/128.f) + 1e-5f);
    float4 g4 = *(const float4*)&lg[j0];
    float4 l4 = *(const float4*)&lb[j0];
    float o0 = (c[0]-mu)*istd*g4.x + l4.x;
    float o1 = (c[1]-mu)*istd*g4.y + l4.y;
    float o2 = (c[2]-mu)*istd*g4.z + l4.z;
    float o3 = (c[3]-mu)*istd*g4.w + l4.w;
    *(float4*)&g_hq[base+j0] = make_float4(o0,o1,o2,o3);
}

__global__ void k_final(const float* __restrict__ b1, const float* __restrict__ W2,
                        const float* __restrict__ b2, float* __restrict__ out){
    int w = (blockIdx.x*blockDim.x + threadIdx.x)>>5;
    if (w>=NN) return;
    int lane = threadIdx.x&31;
    float f0 = fmaxf(g_f[(size_t)w*64 + lane]      + b1[lane],    0.f);
    float f1 = fmaxf(g_f[(size_t)w*64 + 32 + lane] + b1[32+lane], 0.f);
    float l0 = f0*W2[lane]    + f1*W2[32+lane];
    float l1 = f0*W2[64+lane] + f1*W2[96+lane];
    l0 = wredsum(l0); l1 = wredsum(l1);
    if (lane==0){
        out[(size_t)w*2]   = l0 + b2[0];
        out[(size_t)w*2+1] = l1 + b2[1];
    }
}

// ---------------- host driver ------------------------------------------------
static float* symf(const void* s){ void* p=nullptr; cudaGetSymbolAddress(&p, s); return (float*)p; }

extern "C" void kernel_launch(void* const* d_in, const int* in_sizes, int n_in,
                              void* d_out, int out_size){
    const float* x      = (const float*)d_in[0];
    const int*   ei     = (const int*)  d_in[1];
    const float* ts     = (const float*)d_in[2];
    const float* mem    = (const float*)d_in[3];
    const float* W_in   = (const float*)d_in[4];
    const float* b_in   = (const float*)d_in[5];
    const float* W_time = (const float*)d_in[6];
    const float* b_time = (const float*)d_in[7];
    const float* W_ih   = (const float*)d_in[8];
    const float* W_hh   = (const float*)d_in[9];
    const float* b_ih   = (const float*)d_in[10];
    const float* b_hh   = (const float*)d_in[11];
    const float* W_gr   = (const float*)d_in[12];
    const float* b_gr   = (const float*)d_in[13];
    const float* W_gh   = (const float*)d_in[14];
    const float* b_gh   = (const float*)d_in[15];
    const float* ln_pa_g= (const float*)d_in[16];
    const float* ln_pa_b= (const float*)d_in[17];
    const float* Wv     = (const float*)d_in[18];
    const float* bv     = (const float*)d_in[19];
    const float* Wo     = (const float*)d_in[20];
    const float* bo     = (const float*)d_in[21];
    const float* ln_at_g= (const float*)d_in[22];
    const float* ln_at_b= (const float*)d_in[23];
    const float* W1     = (const float*)d_in[24];
    const float* b1     = (const float*)d_in[25];
    const float* W2     = (const float*)d_in[26];
    const float* b2     = (const float*)d_in[27];
    const int* row = ei;
    const int* col = ei + NE;

    float* out        = (float*)d_out;
    float* out_logits = out;
    float* out_newmem = out + 2*(size_t)NN;

    float* p_h    = symf(g_h);
    float* p_agg0 = symf(g_agg0);
    float* p_agg1 = symf(g_agg1);
    float* p_hr   = symf(g_hr);
    float* p_hh2  = symf(g_hh2);
    float* p_hp   = symf(g_hp);
    float* p_att  = symf(g_att);
    float* p_hq   = symf(g_hq);
    float* p_gi   = symf(g_gi);
    float* p_gh   = symf(g_gh);
    float* p_f    = symf(g_f);
    float* p_wf   = symf(g_wf);
    float* p_s0   = symf(g_s0);
    float* p_s1   = symf(g_s1);

    const int EB  = (NE+255)/256;
    const int EWB = (NE*32+255)/256;
    const int NHB = (int)(((size_t)NN*HH+255)/256);
    const int NWB = (NN*32+255)/256;
    const int MY  = (NN+127)/128;
    const int SMM = 2*4*128*24*2;   // 98304 B dynamic smem

    static int smem_set = 0;
    if (!smem_set){
        cudaFuncSetAttribute((const void*)k_mma<0>, cudaFuncAttributeMaxDynamicSharedMemorySize, SMM);
        cudaFuncSetAttribute((const void*)k_mma<1>, cudaFuncAttributeMaxDynamicSharedMemorySize, SMM);
        smem_set = 1;
    }

    // launches 1-5 (so that launch #6 = a big GEMM for ncu -s 5 -c 1)
    k_init<<<1024,256>>>();
    k_wf<<<HH,HH>>>(Wo, Wv);
    k_bvo<<<1,128>>>(bv, Wo, bo);
    k_bsum<<<1,128>>>(b_in, b_time);
    k_hist0<<<264,256>>>(ts);

    // launch #6: GRU gh GEMM (depends only on mem, W_hh) — profiling target
    k_mma<0><<<dim3(3,MY),256,SMM>>>(mem, nullptr, nullptr, W_hh, p_gh, NN, 384, 128,
                                     nullptr, nullptr);

    // edge stats + median
    k_edge1a<<<EB,256>>>(row,col,ts);
    k_scan0<<<1,256>>>();
    k_hist1<<<EB,256>>>(ts);
    k_scan1<<<1,256>>>();
    k_hist2<<<EB,256>>>(ts);
    k_scan2<<<1,256>>>();
    k_ntmm<<<(NN+255)/256,256>>>();

    // h = relu(x@W_in^T + b_in + ntn*wt + bt) + memory (e1 fused in epilogue)
    k_mma<1><<<dim3(1,MY),256,SMM>>>(x, nullptr, nullptr, W_in, p_h, NN, 128, 166,
                                     W_time, mem);

    // GRU gi + combine
    k_mma<0><<<dim3(3,MY),256,SMM>>>(p_h, nullptr, nullptr, W_ih, p_gi, NN, 384, 128,
                                     nullptr, nullptr);
    k_e2<<<NHB,256>>>(b_ih, b_hh, mem, out_newmem);

    // GCN paths
    k_deg<<<EB,256>>>(col, ts);
    k_sscale<<<(NN+255)/256,256>>>();
    k_scatter<<<EWB,256>>>(row, col, ts);
    k_mma<0><<<dim3(1,MY),256,SMM>>>(p_agg0, p_h, p_s0, W_gr, p_hr,  NN, 128, 128,
                                     nullptr, nullptr);
    k_mma<0><<<dim3(1,MY),256,SMM>>>(p_agg1, p_h, p_s1, W_gh, p_hh2, NN, 128, 128,
                                     nullptr, nullptr);
    k_e4<<<NWB,256>>>(b_gr, b_gh, ln_pa_g, ln_pa_b);

    // attention (query path cancels; Wv/Wo fused): att = hp @ (Wo Wv)^T
    k_mma<0><<<dim3(1,MY),256,SMM>>>(p_hp, nullptr, nullptr, p_wf, p_att, NN, 128, 128,
                                     nullptr, nullptr);
    k_e6<<<NWB,256>>>(ln_at_g, ln_at_b);

    // classifier
    k_mma<0><<<dim3(1,MY),256,SMM>>>(p_hq, nullptr, nullptr, W1, p_f, NN, 64, 128,
                                     nullptr, nullptr);
    k_final<<<NWB,256>>>(b1, W2, b2, out_logits);

    (void)in_sizes; (void)n_in; (void)out_size;
}